// round 1
// baseline (speedup 1.0000x reference)
#include <cuda_runtime.h>
#include <cstddef>

// Problem constants
#define Bc   4
#define Sc   1024
#define Dc   1024
#define Hc   16
#define DKc  64
#define Mrows (Bc * Sc)   // 4096

// ---------------------------------------------------------------------------
// Scratch (static __device__ arrays — no allocation at runtime)
// ---------------------------------------------------------------------------
__device__ float g_q  [(size_t)Mrows * Dc];                 // 16 MB
__device__ float g_k  [(size_t)Mrows * Dc];                 // 16 MB
__device__ float g_tk [(size_t)Mrows * Dc];                 // 16 MB
__device__ float g_vv [(size_t)Mrows * Dc];                 // 16 MB (v + t_v fused)
__device__ float g_ctx[(size_t)Mrows * Dc];                 // 16 MB
__device__ float g_scores[(size_t)Bc * Hc * Sc * Sc];       // 256 MB

// ---------------------------------------------------------------------------
// Generic fp32 GEMM: C[M,N] = A[M,K] @ W[K,N] + bias[N] (+ C if accFlag)
// 128x128 tile, BK=8, 256 threads, 8x8 per thread.
// ---------------------------------------------------------------------------
__global__ __launch_bounds__(256) void sgemm_bias_kernel(
    const float* __restrict__ A, const float* __restrict__ W,
    const float* __restrict__ bias, float* __restrict__ C,
    int M, int N, int K, int accFlag)
{
    __shared__ float As[8][132];
    __shared__ float Ws[8][132];

    const int bm  = blockIdx.y * 128;
    const int bn  = blockIdx.x * 128;
    const int tid = threadIdx.x;
    const int tr  = (tid >> 4) * 8;     // 0..120
    const int tc  = (tid & 15) * 8;     // 0..120

    float acc[8][8];
#pragma unroll
    for (int r = 0; r < 8; r++)
#pragma unroll
        for (int c = 0; c < 8; c++) acc[r][c] = 0.f;

    const int am = tid >> 1;            // 0..127
    const int ak = (tid & 1) * 4;       // 0 or 4
    const int wr = tid >> 5;            // 0..7
    const int wc = (tid & 31) * 4;      // 0..124

    for (int k0 = 0; k0 < K; k0 += 8) {
        float4 av = *(const float4*)(A + (size_t)(bm + am) * K + k0 + ak);
        As[ak + 0][am] = av.x;
        As[ak + 1][am] = av.y;
        As[ak + 2][am] = av.z;
        As[ak + 3][am] = av.w;

        float4 wv = *(const float4*)(W + (size_t)(k0 + wr) * N + bn + wc);
        *(float4*)&Ws[wr][wc] = wv;

        __syncthreads();
#pragma unroll
        for (int kk = 0; kk < 8; kk++) {
            float a[8], b[8];
            *(float4*)&a[0] = *(const float4*)&As[kk][tr];
            *(float4*)&a[4] = *(const float4*)&As[kk][tr + 4];
            *(float4*)&b[0] = *(const float4*)&Ws[kk][tc];
            *(float4*)&b[4] = *(const float4*)&Ws[kk][tc + 4];
#pragma unroll
            for (int r = 0; r < 8; r++)
#pragma unroll
                for (int c = 0; c < 8; c++)
                    acc[r][c] += a[r] * b[c];
        }
        __syncthreads();
    }

#pragma unroll
    for (int r = 0; r < 8; r++) {
        const size_t rowoff = (size_t)(bm + tr + r) * N + bn;
#pragma unroll
        for (int c = 0; c < 8; c++) {
            float v = acc[r][c] + bias[bn + tc + c];
            if (accFlag) v += C[rowoff + tc + c];
            C[rowoff + tc + c] = v;
        }
    }
}

// ---------------------------------------------------------------------------
// Scores: scores[bh,i,j] = (q_i . k_j + tk_i . q_j) / 32 + mask[b,0,i,j]
// 64x64 output tile per block; DK=64 handled in one shot; two phases reuse
// the same two smem tiles (Q_i/K_j then Tk_i/Q_j).
// ---------------------------------------------------------------------------
__global__ __launch_bounds__(256) void scores_kernel(const float* __restrict__ mask)
{
    __shared__ float Xs[64][65];
    __shared__ float Ys[64][65];

    const int bh = blockIdx.z;
    const int b  = bh >> 4;
    const int h  = bh & 15;
    const int i0 = blockIdx.y * 64;
    const int j0 = blockIdx.x * 64;
    const int tid = threadIdx.x;
    const int tr = (tid >> 4) * 4;
    const int tc = (tid & 15) * 4;

    const size_t head_base = (size_t)b * Sc * Dc + (size_t)h * DKc;

    float acc[4][4];
#pragma unroll
    for (int r = 0; r < 4; r++)
#pragma unroll
        for (int c = 0; c < 4; c++) acc[r][c] = 0.f;

#pragma unroll
    for (int p = 0; p < 2; p++) {
        const float* Xsrc = p ? g_tk : g_q;   // rows i
        const float* Ysrc = p ? g_q  : g_k;   // rows j
#pragma unroll
        for (int t = 0; t < 4; t++) {
            int e   = tid + t * 256;          // float4 index 0..1023
            int row = e >> 4;
            int d4  = (e & 15) * 4;
            float4 xv = *(const float4*)(Xsrc + head_base + (size_t)(i0 + row) * Dc + d4);
            Xs[row][d4 + 0] = xv.x; Xs[row][d4 + 1] = xv.y;
            Xs[row][d4 + 2] = xv.z; Xs[row][d4 + 3] = xv.w;
            float4 yv = *(const float4*)(Ysrc + head_base + (size_t)(j0 + row) * Dc + d4);
            Ys[row][d4 + 0] = yv.x; Ys[row][d4 + 1] = yv.y;
            Ys[row][d4 + 2] = yv.z; Ys[row][d4 + 3] = yv.w;
        }
        __syncthreads();
#pragma unroll 8
        for (int kk = 0; kk < 64; kk++) {
            float a[4], bb[4];
#pragma unroll
            for (int r = 0; r < 4; r++) a[r]  = Xs[tr + r][kk];
#pragma unroll
            for (int c = 0; c < 4; c++) bb[c] = Ys[tc + c][kk];
#pragma unroll
            for (int r = 0; r < 4; r++)
#pragma unroll
                for (int c = 0; c < 4; c++)
                    acc[r][c] += a[r] * bb[c];
        }
        __syncthreads();
    }

    const float scale = 1.0f / 32.0f;   // 1/sqrt(D), D=1024
    const size_t mbase = (size_t)b * Sc * Sc;
    const size_t sbase = (size_t)bh * Sc * Sc;
#pragma unroll
    for (int r = 0; r < 4; r++) {
        const int i = i0 + tr + r;
#pragma unroll
        for (int c = 0; c < 4; c++) {
            const int j = j0 + tc + c;
            float v = acc[r][c] * scale + mask[mbase + (size_t)i * Sc + j];
            g_scores[sbase + (size_t)i * Sc + j] = v;
        }
    }
}

// ---------------------------------------------------------------------------
// Row softmax over the last axis (1024 elems). One warp per row, fully in
// registers (8 x float4 per lane).
// ---------------------------------------------------------------------------
__global__ __launch_bounds__(256) void softmax_kernel()
{
    const int gwarp = (int)((blockIdx.x * 256 + threadIdx.x) >> 5);
    const int lane  = threadIdx.x & 31;
    float* row = g_scores + (size_t)gwarp * Sc;

    float4 v[8];
    float mx = -1e30f;
#pragma unroll
    for (int t = 0; t < 8; t++) {
        v[t] = *((const float4*)row + lane + t * 32);
        mx = fmaxf(mx, fmaxf(fmaxf(v[t].x, v[t].y), fmaxf(v[t].z, v[t].w)));
    }
#pragma unroll
    for (int o = 16; o > 0; o >>= 1) mx = fmaxf(mx, __shfl_xor_sync(0xffffffffu, mx, o));

    float sum = 0.f;
#pragma unroll
    for (int t = 0; t < 8; t++) {
        v[t].x = __expf(v[t].x - mx);
        v[t].y = __expf(v[t].y - mx);
        v[t].z = __expf(v[t].z - mx);
        v[t].w = __expf(v[t].w - mx);
        sum += v[t].x + v[t].y + v[t].z + v[t].w;
    }
#pragma unroll
    for (int o = 16; o > 0; o >>= 1) sum += __shfl_xor_sync(0xffffffffu, sum, o);

    const float inv = 1.0f / sum;
#pragma unroll
    for (int t = 0; t < 8; t++) {
        v[t].x *= inv; v[t].y *= inv; v[t].z *= inv; v[t].w *= inv;
        *((float4*)row + lane + t * 32) = v[t];
    }
}

// ---------------------------------------------------------------------------
// Context: ctx[b,i,h*64+d] = sum_j P[bh,i,j] * vv[b,j,h*64+d]
// Per block: 64 rows (i) x 64 cols (d=DK), K streamed in chunks of 32.
// Writes directly into merged-head [B,S,D] layout.
// ---------------------------------------------------------------------------
__global__ __launch_bounds__(256) void ctx_kernel()
{
    __shared__ float Ps[32][65];   // [k][i]
    __shared__ float Vs[32][65];   // [k][d]

    const int bh = blockIdx.z;
    const int b  = bh >> 4;
    const int h  = bh & 15;
    const int i0 = blockIdx.x * 64;
    const int tid = threadIdx.x;
    const int tr = (tid >> 4) * 4;
    const int tc = (tid & 15) * 4;

    const size_t pbase = (size_t)bh * Sc * Sc;
    const size_t vbase = (size_t)b * Sc * Dc + (size_t)h * DKc;

    float acc[4][4];
#pragma unroll
    for (int r = 0; r < 4; r++)
#pragma unroll
        for (int c = 0; c < 4; c++) acc[r][c] = 0.f;

    for (int k0 = 0; k0 < Sc; k0 += 32) {
#pragma unroll
        for (int t = 0; t < 2; t++) {
            int e = tid + t * 256;            // float4 index 0..511
            // P tile: 64 rows x 32 cols -> transposed store
            int prow = e >> 3;
            int pc4  = (e & 7) * 4;
            float4 pv = *(const float4*)(g_scores + pbase + (size_t)(i0 + prow) * Sc + k0 + pc4);
            Ps[pc4 + 0][prow] = pv.x; Ps[pc4 + 1][prow] = pv.y;
            Ps[pc4 + 2][prow] = pv.z; Ps[pc4 + 3][prow] = pv.w;
            // VV tile: 32 rows x 64 cols -> direct store
            int vrow = e >> 4;
            int vd4  = (e & 15) * 4;
            float4 vv = *(const float4*)(g_vv + vbase + (size_t)(k0 + vrow) * Dc + vd4);
            Vs[vrow][vd4 + 0] = vv.x; Vs[vrow][vd4 + 1] = vv.y;
            Vs[vrow][vd4 + 2] = vv.z; Vs[vrow][vd4 + 3] = vv.w;
        }
        __syncthreads();
#pragma unroll 8
        for (int kk = 0; kk < 32; kk++) {
            float a[4], bb[4];
#pragma unroll
            for (int r = 0; r < 4; r++) a[r]  = Ps[kk][tr + r];
#pragma unroll
            for (int c = 0; c < 4; c++) bb[c] = Vs[kk][tc + c];
#pragma unroll
            for (int r = 0; r < 4; r++)
#pragma unroll
                for (int c = 0; c < 4; c++)
                    acc[r][c] += a[r] * bb[c];
        }
        __syncthreads();
    }

#pragma unroll
    for (int r = 0; r < 4; r++)
#pragma unroll
        for (int c = 0; c < 4; c++)
            g_ctx[vbase + (size_t)(i0 + tr + r) * Dc + tc + c] = acc[r][c];
}

// ---------------------------------------------------------------------------
// Launch
// ---------------------------------------------------------------------------
extern "C" void kernel_launch(void* const* d_in, const int* in_sizes, int n_in,
                              void* d_out, int out_size)
{
    (void)in_sizes; (void)n_in; (void)out_size;
    const float* query  = (const float*)d_in[0];
    const float* key_   = (const float*)d_in[1];
    const float* value  = (const float*)d_in[2];
    const float* time_k = (const float*)d_in[3];
    const float* time_v = (const float*)d_in[4];
    const float* mask   = (const float*)d_in[5];
    const float* Wq  = (const float*)d_in[6];  const float* bq  = (const float*)d_in[7];
    const float* Wk  = (const float*)d_in[8];  const float* bk  = (const float*)d_in[9];
    const float* Wv  = (const float*)d_in[10]; const float* bv  = (const float*)d_in[11];
    const float* Wtk = (const float*)d_in[12]; const float* btk = (const float*)d_in[13];
    const float* Wtv = (const float*)d_in[14]; const float* btv = (const float*)d_in[15];
    const float* Wm  = (const float*)d_in[16]; const float* bm  = (const float*)d_in[17];
    float* out = (float*)d_out;

    float *pq, *pk, *ptk, *pvv, *pctx;
    cudaGetSymbolAddress((void**)&pq,   g_q);
    cudaGetSymbolAddress((void**)&pk,   g_k);
    cudaGetSymbolAddress((void**)&ptk,  g_tk);
    cudaGetSymbolAddress((void**)&pvv,  g_vv);
    cudaGetSymbolAddress((void**)&pctx, g_ctx);

    dim3 gg(Dc / 128, Mrows / 128);   // (8, 32)

    // Projections
    sgemm_bias_kernel<<<gg, 256>>>(query,  Wq,  bq,  pq,  Mrows, Dc, Dc, 0);
    sgemm_bias_kernel<<<gg, 256>>>(key_,   Wk,  bk,  pk,  Mrows, Dc, Dc, 0);
    sgemm_bias_kernel<<<gg, 256>>>(time_k, Wtk, btk, ptk, Mrows, Dc, Dc, 0);
    sgemm_bias_kernel<<<gg, 256>>>(value,  Wv,  bv,  pvv, Mrows, Dc, Dc, 0);
    sgemm_bias_kernel<<<gg, 256>>>(time_v, Wtv, btv, pvv, Mrows, Dc, Dc, 1); // vv = v + t_v

    // Attention core
    scores_kernel<<<dim3(Sc / 64, Sc / 64, Bc * Hc), 256>>>(mask);
    softmax_kernel<<<(Bc * Hc * Sc) / 8, 256>>>();          // 8 rows per 256-thr block
    ctx_kernel<<<dim3(Sc / 64, 1, Bc * Hc), 256>>>();

    // Output projection
    sgemm_bias_kernel<<<gg, 256>>>(pctx, Wm, bm, out, Mrows, Dc, Dc, 0);
}

// round 3
// speedup vs baseline: 1.8559x; 1.8559x over previous
#include <cuda_runtime.h>
#include <cstdint>
#include <cstddef>

// Problem constants
#define Bc   4
#define Sc   1024
#define Dc   1024
#define Hc   16
#define DKc  64
#define Mrows (Bc * Sc)   // 4096

// ---------------------------------------------------------------------------
// Scratch (static __device__ arrays — no allocation at runtime)
// ---------------------------------------------------------------------------
__device__ float g_q  [(size_t)Mrows * Dc];                 // 16 MB
__device__ float g_k  [(size_t)Mrows * Dc];                 // 16 MB
__device__ float g_tk [(size_t)Mrows * Dc];                 // 16 MB
__device__ float g_vv [(size_t)Mrows * Dc];                 // 16 MB (v + t_v fused)
__device__ float g_ctx[(size_t)Mrows * Dc];                 // 16 MB
__device__ float g_scores[(size_t)Bc * Hc * Sc * Sc];       // 256 MB
__device__ float g_wt [6u * 1024u * 1024u];                 // 24 MB (transposed weights)

// ---------------------------------------------------------------------------
// tf32 mma.sync helpers
// ---------------------------------------------------------------------------
__device__ __forceinline__ uint32_t f2tf32(float f) {
    uint32_t o;
    asm("cvt.rna.tf32.f32 %0, %1;" : "=r"(o) : "f"(f));
    return o;
}

__device__ __forceinline__ void mma_tf32(float d[4], const uint32_t a[4], const uint32_t b[2]) {
    asm volatile("mma.sync.aligned.m16n8k8.row.col.f32.tf32.tf32.f32 "
        "{%0,%1,%2,%3}, {%4,%5,%6,%7}, {%8,%9}, {%0,%1,%2,%3};"
        : "+f"(d[0]), "+f"(d[1]), "+f"(d[2]), "+f"(d[3])
        : "r"(a[0]), "r"(a[1]), "r"(a[2]), "r"(a[3]), "r"(b[0]), "r"(b[1]));
}

// ---------------------------------------------------------------------------
// Staging: gmem fp32 -> smem tf32 in FRAGMENT order.
// A-side (rows = M, 128 rows x 32 k): block (ks*8 + mtile) of 128 regs:
//   lane = ((mr&7)<<2)|(kc&3),  reg = (mr>=8) + 2*(kc>=4)
// B-side (rows = N, 128 rows x 32 k): block (ks*16 + ntile) of 64 regs:
//   lane = (nr<<2)|(kc&3),      reg = (kc>=4)
// ---------------------------------------------------------------------------
__device__ __forceinline__ void stage_A128(const float* __restrict__ src, size_t rowStride,
                                           uint32_t* __restrict__ dst, int tid) {
#pragma unroll
    for (int t = 0; t < 4; ++t) {
        int idx = tid + t * 256;          // 1024 float4 slots
        int row = idx >> 3;               // 0..127
        int kq  = idx & 7;
        float4 v = *(const float4*)(src + (size_t)row * rowStride + kq * 4);
        int mt = row >> 4, mr = row & 15;
        float vv[4] = {v.x, v.y, v.z, v.w};
#pragma unroll
        for (int e = 0; e < 4; ++e) {
            int k = kq * 4 + e, ks = k >> 3, kc = k & 7;
            int lane = ((mr & 7) << 2) | (kc & 3);
            int reg  = ((mr >> 3) & 1) | (((kc >> 2) & 1) << 1);
            dst[(ks * 8 + mt) * 128 + lane * 4 + reg] = f2tf32(vv[e]);
        }
    }
}

__device__ __forceinline__ void stage_B128(const float* __restrict__ src, size_t rowStride,
                                           uint32_t* __restrict__ dst, int tid) {
#pragma unroll
    for (int t = 0; t < 4; ++t) {
        int idx = tid + t * 256;
        int row = idx >> 3;               // n 0..127
        int kq  = idx & 7;
        float4 v = *(const float4*)(src + (size_t)row * rowStride + kq * 4);
        int nt = row >> 3, nr = row & 7;
        float vv[4] = {v.x, v.y, v.z, v.w};
#pragma unroll
        for (int e = 0; e < 4; ++e) {
            int k = kq * 4 + e, ks = k >> 3, kc = k & 7;
            int lane = (nr << 2) | (kc & 3);
            int reg  = (kc >> 2) & 1;
            dst[(ks * 16 + nt) * 64 + lane * 2 + reg] = f2tf32(vv[e]);
        }
    }
}

// B staging for ctx: vv tile is 32 rows (j = k-dim) x 64 cols (d = n-dim)
__device__ __forceinline__ void stage_Bvv(const float* __restrict__ src, size_t rowStride,
                                          uint32_t* __restrict__ dst, int tid) {
#pragma unroll
    for (int t = 0; t < 2; ++t) {
        int idx = tid + t * 256;          // 512 float4 slots
        int row = idx >> 4;               // j 0..31 (k-dim)
        int dq  = idx & 15;
        float4 v = *(const float4*)(src + (size_t)row * rowStride + dq * 4);
        int ks = row >> 3, kc = row & 7;
        float vv[4] = {v.x, v.y, v.z, v.w};
#pragma unroll
        for (int e = 0; e < 4; ++e) {
            int d = dq * 4 + e;
            int nt = d >> 3, nr = d & 7;
            int lane = (nr << 2) | (kc & 3);
            int reg  = (kc >> 2) & 1;
            dst[(ks * 8 + nt) * 64 + lane * 2 + reg] = f2tf32(vv[e]);
        }
    }
}

// 128x128 tile compute over one 32-k chunk
__device__ __forceinline__ void compute128x128(const uint32_t* __restrict__ As,
                                               const uint32_t* __restrict__ Bs,
                                               float acc[4][4][4],
                                               int warp_m, int warp_n, int lane) {
#pragma unroll
    for (int s = 0; s < 4; ++s) {
        uint32_t b[4][2];
#pragma unroll
        for (int nt = 0; nt < 4; ++nt) {
            uint2 bv = *(const uint2*)(Bs + (s * 16 + warp_n * 4 + nt) * 64 + lane * 2);
            b[nt][0] = bv.x; b[nt][1] = bv.y;
        }
#pragma unroll
        for (int mt = 0; mt < 4; ++mt) {
            uint4 av = *(const uint4*)(As + (s * 8 + warp_m * 4 + mt) * 128 + lane * 4);
            uint32_t a[4] = {av.x, av.y, av.z, av.w};
#pragma unroll
            for (int nt = 0; nt < 4; ++nt) mma_tf32(acc[mt][nt], a, b[nt]);
        }
    }
}

// ---------------------------------------------------------------------------
// Transpose: g_wt[z] = W_z^T
// ---------------------------------------------------------------------------
__global__ __launch_bounds__(256) void transpose6_kernel(
    const float* __restrict__ W0, const float* __restrict__ W1,
    const float* __restrict__ W2, const float* __restrict__ W3,
    const float* __restrict__ W4, const float* __restrict__ W5)
{
    __shared__ float tile[32][33];
    const float* src;
    switch (blockIdx.z) {
        case 0: src = W0; break; case 1: src = W1; break;
        case 2: src = W2; break; case 3: src = W3; break;
        case 4: src = W4; break; default: src = W5; break;
    }
    float* dst = g_wt + (size_t)blockIdx.z * 1024u * 1024u;

    int tx = threadIdx.x, ty = threadIdx.y;
    int x = blockIdx.x * 32 + tx;
    int y = blockIdx.y * 32 + ty;
#pragma unroll
    for (int j = 0; j < 32; j += 8)
        tile[ty + j][tx] = src[(size_t)(y + j) * 1024 + x];
    __syncthreads();
    int x2 = blockIdx.y * 32 + tx;
    int y2 = blockIdx.x * 32 + ty;
#pragma unroll
    for (int j = 0; j < 32; j += 8)
        dst[(size_t)(y2 + j) * 1024 + x2] = tile[tx][ty + j];
}

// ---------------------------------------------------------------------------
// GEMM: C[4096,1024] = A @ BT^T + bias (+C if accFlag). 128x128 per CTA.
// ---------------------------------------------------------------------------
__global__ __launch_bounds__(256) void gemm_tf32_mma(
    const float* __restrict__ A, const float* __restrict__ BT,
    const float* __restrict__ bias, float* __restrict__ C, int accFlag)
{
    extern __shared__ uint32_t sm[];
    uint32_t* Abuf[2] = { sm, sm + 4096 };
    uint32_t* Bbuf[2] = { sm + 8192, sm + 12288 };

    const int tid = threadIdx.x, lane = tid & 31, wid = tid >> 5;
    const int warp_m = wid >> 2, warp_n = wid & 3;
    const int bm = blockIdx.y * 128, bn = blockIdx.x * 128;

    float acc[4][4][4];
#pragma unroll
    for (int i = 0; i < 4; i++)
#pragma unroll
        for (int j = 0; j < 4; j++)
#pragma unroll
            for (int q = 0; q < 4; q++) acc[i][j][q] = 0.f;

    stage_A128(A  + (size_t)bm * Dc, Dc, Abuf[0], tid);
    stage_B128(BT + (size_t)bn * Dc, Dc, Bbuf[0], tid);
    __syncthreads();

    for (int c = 0; c < 32; ++c) {
        const int p = c & 1;
        if (c + 1 < 32) {
            stage_A128(A  + (size_t)bm * Dc + (c + 1) * 32, Dc, Abuf[1 - p], tid);
            stage_B128(BT + (size_t)bn * Dc + (c + 1) * 32, Dc, Bbuf[1 - p], tid);
        }
        compute128x128(Abuf[p], Bbuf[p], acc, warp_m, warp_n, lane);
        __syncthreads();
    }

    const int r0 = bm + warp_m * 64 + (lane >> 2);
    const int c0 = bn + warp_n * 32 + (lane & 3) * 2;
#pragma unroll
    for (int mt = 0; mt < 4; ++mt) {
#pragma unroll
        for (int nt = 0; nt < 4; ++nt) {
            int col = c0 + nt * 8;
            float2 bv = *(const float2*)(bias + col);
            size_t off0 = (size_t)(r0 + mt * 16) * Dc + col;
            size_t off1 = off0 + 8 * (size_t)Dc;
            float2 o0 = { acc[mt][nt][0] + bv.x, acc[mt][nt][1] + bv.y };
            float2 o1 = { acc[mt][nt][2] + bv.x, acc[mt][nt][3] + bv.y };
            if (accFlag) {
                float2 p0 = *(const float2*)(C + off0);
                float2 p1 = *(const float2*)(C + off1);
                o0.x += p0.x; o0.y += p0.y; o1.x += p1.x; o1.y += p1.y;
            }
            *(float2*)(C + off0) = o0;
            *(float2*)(C + off1) = o1;
        }
    }
}

// ---------------------------------------------------------------------------
// Scores: scores[bh,i,j] = (q_i.k_j + tk_i.q_j)/32 + mask. 128x128 per CTA.
// K = 64 per phase -> 4 chunks total (2 phases x 2).
// ---------------------------------------------------------------------------
__global__ __launch_bounds__(256) void scores_mma(const float* __restrict__ mask)
{
    extern __shared__ uint32_t sm[];
    uint32_t* Abuf[2] = { sm, sm + 4096 };
    uint32_t* Bbuf[2] = { sm + 8192, sm + 12288 };

    const int tid = threadIdx.x, lane = tid & 31, wid = tid >> 5;
    const int warp_m = wid >> 2, warp_n = wid & 3;
    const int bh = blockIdx.z;
    const int b  = bh >> 4, h = bh & 15;
    const int i0 = blockIdx.y * 128, j0 = blockIdx.x * 128;
    const size_t head = (size_t)b * Sc * Dc + (size_t)h * DKc;

    const float* Xsrc[4] = { g_q, g_q, g_tk, g_tk };   // rows i
    const float* Ysrc[4] = { g_k, g_k, g_q,  g_q  };   // rows j
    const int koff[4] = { 0, 32, 0, 32 };

    float acc[4][4][4];
#pragma unroll
    for (int i = 0; i < 4; i++)
#pragma unroll
        for (int j = 0; j < 4; j++)
#pragma unroll
            for (int q = 0; q < 4; q++) acc[i][j][q] = 0.f;

    stage_A128(Xsrc[0] + head + (size_t)i0 * Dc + koff[0], Dc, Abuf[0], tid);
    stage_B128(Ysrc[0] + head + (size_t)j0 * Dc + koff[0], Dc, Bbuf[0], tid);
    __syncthreads();

    for (int c = 0; c < 4; ++c) {
        const int p = c & 1;
        if (c + 1 < 4) {
            stage_A128(Xsrc[c + 1] + head + (size_t)i0 * Dc + koff[c + 1], Dc, Abuf[1 - p], tid);
            stage_B128(Ysrc[c + 1] + head + (size_t)j0 * Dc + koff[c + 1], Dc, Bbuf[1 - p], tid);
        }
        compute128x128(Abuf[p], Bbuf[p], acc, warp_m, warp_n, lane);
        __syncthreads();
    }

    const float scale = 1.0f / 32.0f;
    const size_t mbase = (size_t)b * Sc * Sc;
    const size_t sbase = (size_t)bh * Sc * Sc;
    const int ri = i0 + warp_m * 64 + (lane >> 2);
    const int cj = j0 + warp_n * 32 + (lane & 3) * 2;
#pragma unroll
    for (int mt = 0; mt < 4; ++mt) {
#pragma unroll
        for (int nt = 0; nt < 4; ++nt) {
            int i = ri + mt * 16;
            int j = cj + nt * 8;
            size_t m0 = mbase + (size_t)i * Sc + j;
            size_t s0 = sbase + (size_t)i * Sc + j;
            float2 mk0 = *(const float2*)(mask + m0);
            float2 mk1 = *(const float2*)(mask + m0 + 8 * (size_t)Sc);
            float2 o0 = { acc[mt][nt][0] * scale + mk0.x, acc[mt][nt][1] * scale + mk0.y };
            float2 o1 = { acc[mt][nt][2] * scale + mk1.x, acc[mt][nt][3] * scale + mk1.y };
            *(float2*)(g_scores + s0) = o0;
            *(float2*)(g_scores + s0 + 8 * (size_t)Sc) = o1;
        }
    }
}

// ---------------------------------------------------------------------------
// Row softmax over the last axis (1024 elems), one warp per row.
// ---------------------------------------------------------------------------
__global__ __launch_bounds__(256) void softmax_kernel()
{
    const int gwarp = (int)((blockIdx.x * 256 + threadIdx.x) >> 5);
    const int lane  = threadIdx.x & 31;
    float* row = g_scores + (size_t)gwarp * Sc;

    float4 v[8];
    float mx = -1e30f;
#pragma unroll
    for (int t = 0; t < 8; t++) {
        v[t] = *((const float4*)row + lane + t * 32);
        mx = fmaxf(mx, fmaxf(fmaxf(v[t].x, v[t].y), fmaxf(v[t].z, v[t].w)));
    }
#pragma unroll
    for (int o = 16; o > 0; o >>= 1) mx = fmaxf(mx, __shfl_xor_sync(0xffffffffu, mx, o));

    float sum = 0.f;
#pragma unroll
    for (int t = 0; t < 8; t++) {
        v[t].x = __expf(v[t].x - mx);
        v[t].y = __expf(v[t].y - mx);
        v[t].z = __expf(v[t].z - mx);
        v[t].w = __expf(v[t].w - mx);
        sum += v[t].x + v[t].y + v[t].z + v[t].w;
    }
#pragma unroll
    for (int o = 16; o > 0; o >>= 1) sum += __shfl_xor_sync(0xffffffffu, sum, o);

    const float inv = 1.0f / sum;
#pragma unroll
    for (int t = 0; t < 8; t++) {
        v[t].x *= inv; v[t].y *= inv; v[t].z *= inv; v[t].w *= inv;
        *((float4*)row + lane + t * 32) = v[t];
    }
}

// ---------------------------------------------------------------------------
// Context: ctx[b,i,h*64+d] = sum_j P[bh,i,j]*vv[b,j,h*64+d]. 128i x 64d / CTA.
// K = 1024 over j, chunks of 32. Warp tile 64m x 16n.
// ---------------------------------------------------------------------------
__global__ __launch_bounds__(256) void ctx_mma()
{
    extern __shared__ uint32_t sm[];
    uint32_t* Abuf[2] = { sm, sm + 4096 };
    uint32_t* Bbuf[2] = { sm + 8192, sm + 8192 + 2048 };

    const int tid = threadIdx.x, lane = tid & 31, wid = tid >> 5;
    const int warp_m = wid >> 2, warp_n = wid & 3;
    const int bh = blockIdx.z;
    const int b  = bh >> 4, h = bh & 15;
    const int i0 = blockIdx.x * 128;
    const size_t pbase = (size_t)bh * Sc * Sc;
    const size_t vbase = (size_t)b * Sc * Dc + (size_t)h * DKc;

    float acc[4][2][4];
#pragma unroll
    for (int i = 0; i < 4; i++)
#pragma unroll
        for (int j = 0; j < 2; j++)
#pragma unroll
            for (int q = 0; q < 4; q++) acc[i][j][q] = 0.f;

    stage_A128(g_scores + pbase + (size_t)i0 * Sc, Sc, Abuf[0], tid);
    stage_Bvv(g_vv + vbase, Dc, Bbuf[0], tid);
    __syncthreads();

    for (int c = 0; c < 32; ++c) {
        const int p = c & 1;
        if (c + 1 < 32) {
            stage_A128(g_scores + pbase + (size_t)i0 * Sc + (c + 1) * 32, Sc, Abuf[1 - p], tid);
            stage_Bvv(g_vv + vbase + (size_t)(c + 1) * 32 * Dc, Dc, Bbuf[1 - p], tid);
        }
        // compute: 128m x 64n
        const uint32_t* As = Abuf[p];
        const uint32_t* Bs = Bbuf[p];
#pragma unroll
        for (int s = 0; s < 4; ++s) {
            uint32_t bfr[2][2];
#pragma unroll
            for (int nt = 0; nt < 2; ++nt) {
                uint2 bv = *(const uint2*)(Bs + (s * 8 + warp_n * 2 + nt) * 64 + lane * 2);
                bfr[nt][0] = bv.x; bfr[nt][1] = bv.y;
            }
#pragma unroll
            for (int mt = 0; mt < 4; ++mt) {
                uint4 av = *(const uint4*)(As + (s * 8 + warp_m * 4 + mt) * 128 + lane * 4);
                uint32_t a[4] = {av.x, av.y, av.z, av.w};
#pragma unroll
                for (int nt = 0; nt < 2; ++nt) mma_tf32(acc[mt][nt], a, bfr[nt]);
            }
        }
        __syncthreads();
    }

    const int ri = i0 + warp_m * 64 + (lane >> 2);
    const int cd = warp_n * 16 + (lane & 3) * 2;
#pragma unroll
    for (int mt = 0; mt < 4; ++mt) {
#pragma unroll
        for (int nt = 0; nt < 2; ++nt) {
            int i = ri + mt * 16;
            int d = cd + nt * 8;
            size_t off0 = vbase + (size_t)i * Dc + d;
            size_t off1 = off0 + 8 * (size_t)Dc;
            float2 o0 = { acc[mt][nt][0], acc[mt][nt][1] };
            float2 o1 = { acc[mt][nt][2], acc[mt][nt][3] };
            *(float2*)(g_ctx + off0) = o0;
            *(float2*)(g_ctx + off1) = o1;
        }
    }
}

// ---------------------------------------------------------------------------
// Launch
// ---------------------------------------------------------------------------
#define GEMM_SMEM   65536
#define CTX_SMEM    49152

extern "C" void kernel_launch(void* const* d_in, const int* in_sizes, int n_in,
                              void* d_out, int out_size)
{
    (void)in_sizes; (void)n_in; (void)out_size;
    const float* query  = (const float*)d_in[0];
    const float* key_   = (const float*)d_in[1];
    const float* value  = (const float*)d_in[2];
    const float* time_k = (const float*)d_in[3];
    const float* time_v = (const float*)d_in[4];
    const float* mask   = (const float*)d_in[5];
    const float* Wq  = (const float*)d_in[6];  const float* bq  = (const float*)d_in[7];
    const float* Wk  = (const float*)d_in[8];  const float* bk  = (const float*)d_in[9];
    const float* Wv  = (const float*)d_in[10]; const float* bv  = (const float*)d_in[11];
    const float* Wtk = (const float*)d_in[12]; const float* btk = (const float*)d_in[13];
    const float* Wtv = (const float*)d_in[14]; const float* btv = (const float*)d_in[15];
    const float* Wm  = (const float*)d_in[16]; const float* bm  = (const float*)d_in[17];
    float* out = (float*)d_out;

    float *pq, *pk, *ptk, *pvv, *pctx, *pwt;
    cudaGetSymbolAddress((void**)&pq,   g_q);
    cudaGetSymbolAddress((void**)&pk,   g_k);
    cudaGetSymbolAddress((void**)&ptk,  g_tk);
    cudaGetSymbolAddress((void**)&pvv,  g_vv);
    cudaGetSymbolAddress((void**)&pctx, g_ctx);
    cudaGetSymbolAddress((void**)&pwt,  g_wt);

    cudaFuncSetAttribute(gemm_tf32_mma, cudaFuncAttributeMaxDynamicSharedMemorySize, GEMM_SMEM);
    cudaFuncSetAttribute(scores_mma,    cudaFuncAttributeMaxDynamicSharedMemorySize, GEMM_SMEM);
    cudaFuncSetAttribute(ctx_mma,       cudaFuncAttributeMaxDynamicSharedMemorySize, CTX_SMEM);

    // Transpose all 6 weight matrices: order Wq, Wk, Wtk, Wv, Wtv, Wm
    transpose6_kernel<<<dim3(32, 32, 6), dim3(32, 8)>>>(Wq, Wk, Wtk, Wv, Wtv, Wm);

    const size_t WSZ = 1024u * 1024u;
    dim3 gg(Dc / 128, Mrows / 128);   // (8, 32)

    // Projections (tf32 mma.sync)
    gemm_tf32_mma<<<gg, 256, GEMM_SMEM>>>(query,  pwt + 0 * WSZ, bq,  pq,  0);
    gemm_tf32_mma<<<gg, 256, GEMM_SMEM>>>(key_,   pwt + 1 * WSZ, bk,  pk,  0);
    gemm_tf32_mma<<<gg, 256, GEMM_SMEM>>>(time_k, pwt + 2 * WSZ, btk, ptk, 0);
    gemm_tf32_mma<<<gg, 256, GEMM_SMEM>>>(value,  pwt + 3 * WSZ, bv,  pvv, 0);
    gemm_tf32_mma<<<gg, 256, GEMM_SMEM>>>(time_v, pwt + 4 * WSZ, btv, pvv, 1);  // vv = v + t_v

    // Attention core (tf32 mma.sync)
    scores_mma<<<dim3(Sc / 128, Sc / 128, Bc * Hc), 256, GEMM_SMEM>>>(mask);
    softmax_kernel<<<(Bc * Hc * Sc) / 8, 256>>>();
    ctx_mma<<<dim3(Sc / 128, 1, Bc * Hc), 256, CTX_SMEM>>>();

    // Output projection
    gemm_tf32_mma<<<gg, 256, GEMM_SMEM>>>(pctx, pwt + 5 * WSZ, bm, out, 0);
}

// round 4
// speedup vs baseline: 3.0834x; 1.6614x over previous
#include <cuda_runtime.h>
#include <cstdint>
#include <cstddef>

// Problem constants
#define Bc   4
#define Sc   1024
#define Dc   1024
#define Hc   16
#define DKc  64
#define Mrows (Bc * Sc)   // 4096

// ---------------------------------------------------------------------------
// Scratch (static __device__ arrays — no allocation at runtime)
// ---------------------------------------------------------------------------
__device__ float g_q  [(size_t)Mrows * Dc];                 // 16 MB
__device__ float g_k  [(size_t)Mrows * Dc];                 // 16 MB
__device__ float g_tk [(size_t)Mrows * Dc];                 // 16 MB
__device__ float g_vv [(size_t)Mrows * Dc];                 // 16 MB (v + t_v fused)
__device__ float g_ctx[(size_t)Mrows * Dc];                 // 16 MB
__device__ float g_scores[(size_t)Bc * Hc * Sc * Sc];       // 256 MB
__device__ float g_wt [6u * 1024u * 1024u];                 // 24 MB (transposed weights)

// ---------------------------------------------------------------------------
// Helpers
// ---------------------------------------------------------------------------
__device__ __forceinline__ uint32_t smem_u32(const void* p) {
    uint32_t a;
    asm("{ .reg .u64 t; cvta.to.shared.u64 t, %1; cvt.u32.u64 %0, t; }" : "=r"(a) : "l"(p));
    return a;
}

__device__ __forceinline__ void cp16(uint32_t dst, const void* src) {
    asm volatile("cp.async.cg.shared.global [%0], [%1], 16;" :: "r"(dst), "l"(src));
}
#define CP_COMMIT() asm volatile("cp.async.commit_group;" ::: "memory")
#define CP_WAIT1()  asm volatile("cp.async.wait_group 1;" ::: "memory")
#define CP_WAIT0()  asm volatile("cp.async.wait_group 0;" ::: "memory")

__device__ __forceinline__ uint32_t f2tf32(float f) {
    uint32_t o;
    asm("cvt.rna.tf32.f32 %0, %1;" : "=r"(o) : "f"(f));
    return o;
}

__device__ __forceinline__ void mma_tf32(float d[4], const uint32_t a[4], const uint32_t b[2]) {
    asm volatile("mma.sync.aligned.m16n8k8.row.col.f32.tf32.tf32.f32 "
        "{%0,%1,%2,%3}, {%4,%5,%6,%7}, {%8,%9}, {%0,%1,%2,%3};"
        : "+f"(d[0]), "+f"(d[1]), "+f"(d[2]), "+f"(d[3])
        : "r"(a[0]), "r"(a[1]), "r"(a[2]), "r"(a[3]), "r"(b[0]), "r"(b[1]));
}

// Padded strides (words). 36 => gather bank = lane, conflict-free.
#define PAD_AB  36
#define AWORDS  (128 * PAD_AB)      // 4608
#define STG_W   (2 * AWORDS)        // 9216 words per stage (A + B)
#define PAD_VV  72
#define VWORDS  (32 * PAD_VV)       // 2304
#define CTXSTG_W (AWORDS + VWORDS)  // 6912

// ---------------------------------------------------------------------------
// Transpose: g_wt[z] = W_z^T
// ---------------------------------------------------------------------------
__global__ __launch_bounds__(256) void transpose6_kernel(
    const float* __restrict__ W0, const float* __restrict__ W1,
    const float* __restrict__ W2, const float* __restrict__ W3,
    const float* __restrict__ W4, const float* __restrict__ W5)
{
    __shared__ float tile[32][33];
    const float* src;
    switch (blockIdx.z) {
        case 0: src = W0; break; case 1: src = W1; break;
        case 2: src = W2; break; case 3: src = W3; break;
        case 4: src = W4; break; default: src = W5; break;
    }
    float* dst = g_wt + (size_t)blockIdx.z * 1024u * 1024u;

    int tx = threadIdx.x, ty = threadIdx.y;
    int x = blockIdx.x * 32 + tx;
    int y = blockIdx.y * 32 + ty;
#pragma unroll
    for (int j = 0; j < 32; j += 8)
        tile[ty + j][tx] = src[(size_t)(y + j) * 1024 + x];
    __syncthreads();
    int x2 = blockIdx.y * 32 + tx;
    int y2 = blockIdx.x * 32 + ty;
#pragma unroll
    for (int j = 0; j < 32; j += 8)
        dst[(size_t)(y2 + j) * 1024 + x2] = tile[tx][ty + j];
}

// ---------------------------------------------------------------------------
// Stage one 128x32 fp32 tile (row stride ldg) into padded smem (PAD_AB).
// 1024 x 16B copies; 4 per thread. Fully coalesced, async.
// ---------------------------------------------------------------------------
__device__ __forceinline__ void cp_tile128(uint32_t smbase, const float* __restrict__ src,
                                           size_t ldg, int tid) {
#pragma unroll
    for (int t = 0; t < 4; ++t) {
        int slot = tid + t * 256;
        int row = slot >> 3;
        int seg = slot & 7;
        cp16(smbase + (uint32_t)(row * PAD_AB + seg * 4) * 4,
             src + (size_t)row * ldg + seg * 4);
    }
}

// Stage the 32x64 vv tile (k-major rows, stride ldg) into padded smem (PAD_VV).
__device__ __forceinline__ void cp_tilevv(uint32_t smbase, const float* __restrict__ src,
                                          size_t ldg, int tid) {
#pragma unroll
    for (int t = 0; t < 2; ++t) {
        int slot = tid + t * 256;
        int row = slot >> 4;        // k 0..31
        int seg = slot & 15;        // 16B segment within 64 floats
        cp16(smbase + (uint32_t)(row * PAD_VV + seg * 4) * 4,
             src + (size_t)row * ldg + seg * 4);
    }
}

// ---------------------------------------------------------------------------
// Compute one 32-k chunk of a 128x128 tile from raw padded smem tiles.
// Conflict-free LDS.32 gathers (bank == lane), cvt in regs, mma.
// ---------------------------------------------------------------------------
__device__ __forceinline__ void compute128x128(const float* __restrict__ As,
                                               const float* __restrict__ Bs,
                                               float acc[4][4][4],
                                               int warp_m, int warp_n, int lane) {
    const int lr = lane >> 2;       // 0..7
    const int lc = lane & 3;        // 0..3
#pragma unroll
    for (int s = 0; s < 4; ++s) {
        const int kk = s * 8 + lc;
        uint32_t bfr[4][2];
#pragma unroll
        for (int nt = 0; nt < 4; ++nt) {
            int n = warp_n * 32 + nt * 8 + lr;
            bfr[nt][0] = f2tf32(Bs[n * PAD_AB + kk]);
            bfr[nt][1] = f2tf32(Bs[n * PAD_AB + kk + 4]);
        }
#pragma unroll
        for (int mt = 0; mt < 4; ++mt) {
            int m = warp_m * 64 + mt * 16 + lr;
            uint32_t a[4];
            a[0] = f2tf32(As[m * PAD_AB + kk]);
            a[1] = f2tf32(As[(m + 8) * PAD_AB + kk]);
            a[2] = f2tf32(As[m * PAD_AB + kk + 4]);
            a[3] = f2tf32(As[(m + 8) * PAD_AB + kk + 4]);
#pragma unroll
            for (int nt = 0; nt < 4; ++nt) mma_tf32(acc[mt][nt], a, bfr[nt]);
        }
    }
}

// ---------------------------------------------------------------------------
// GEMM: C[4096,1024] = A @ BT^T + bias (+C if accFlag). 128x128 per CTA.
// ---------------------------------------------------------------------------
__global__ __launch_bounds__(256) void gemm_tf32_mma(
    const float* __restrict__ A, const float* __restrict__ BT,
    const float* __restrict__ bias, float* __restrict__ C, int accFlag)
{
    extern __shared__ float sm[];
    const uint32_t smbase = smem_u32(sm);

    const int tid = threadIdx.x, lane = tid & 31, wid = tid >> 5;
    const int warp_m = wid >> 2, warp_n = wid & 3;
    const int bm = blockIdx.y * 128, bn = blockIdx.x * 128;

    float acc[4][4][4];
#pragma unroll
    for (int i = 0; i < 4; i++)
#pragma unroll
        for (int j = 0; j < 4; j++)
#pragma unroll
            for (int q = 0; q < 4; q++) acc[i][j][q] = 0.f;

    // prologue: stage chunk 0 into buffer 0
    cp_tile128(smbase, A + (size_t)bm * Dc, Dc, tid);
    cp_tile128(smbase + AWORDS * 4, BT + (size_t)bn * Dc, Dc, tid);
    CP_COMMIT();

    for (int c = 0; c < 32; ++c) {
        const int p = c & 1;
        if (c + 1 < 32) {
            const uint32_t nb = smbase + (uint32_t)(1 - p) * STG_W * 4;
            cp_tile128(nb, A + (size_t)bm * Dc + (c + 1) * 32, Dc, tid);
            cp_tile128(nb + AWORDS * 4, BT + (size_t)bn * Dc + (c + 1) * 32, Dc, tid);
            CP_COMMIT();
            CP_WAIT1();
        } else {
            CP_WAIT0();
        }
        __syncthreads();
        const float* As = sm + (size_t)p * STG_W;
        compute128x128(As, As + AWORDS, acc, warp_m, warp_n, lane);
        __syncthreads();
    }

    const int r0 = bm + warp_m * 64 + (lane >> 2);
    const int c0 = bn + warp_n * 32 + (lane & 3) * 2;
#pragma unroll
    for (int mt = 0; mt < 4; ++mt) {
#pragma unroll
        for (int nt = 0; nt < 4; ++nt) {
            int col = c0 + nt * 8;
            float2 bv = *(const float2*)(bias + col);
            size_t off0 = (size_t)(r0 + mt * 16) * Dc + col;
            size_t off1 = off0 + 8 * (size_t)Dc;
            float2 o0 = { acc[mt][nt][0] + bv.x, acc[mt][nt][1] + bv.y };
            float2 o1 = { acc[mt][nt][2] + bv.x, acc[mt][nt][3] + bv.y };
            if (accFlag) {
                float2 p0 = *(const float2*)(C + off0);
                float2 p1 = *(const float2*)(C + off1);
                o0.x += p0.x; o0.y += p0.y; o1.x += p1.x; o1.y += p1.y;
            }
            *(float2*)(C + off0) = o0;
            *(float2*)(C + off1) = o1;
        }
    }
}

// ---------------------------------------------------------------------------
// Scores: scores[bh,i,j] = (q_i.k_j + tk_i.q_j)/32 + mask. 128x128 per CTA.
// 4 chunks: (q,k | k0), (q,k | k32), (tk,q | k0), (tk,q | k32)
// ---------------------------------------------------------------------------
__global__ __launch_bounds__(256) void scores_mma(const float* __restrict__ mask)
{
    extern __shared__ float sm[];
    const uint32_t smbase = smem_u32(sm);

    const int tid = threadIdx.x, lane = tid & 31, wid = tid >> 5;
    const int warp_m = wid >> 2, warp_n = wid & 3;
    const int bh = blockIdx.z;
    const int b  = bh >> 4, h = bh & 15;
    const int i0 = blockIdx.y * 128, j0 = blockIdx.x * 128;
    const size_t head = (size_t)b * Sc * Dc + (size_t)h * DKc;

    float acc[4][4][4];
#pragma unroll
    for (int i = 0; i < 4; i++)
#pragma unroll
        for (int j = 0; j < 4; j++)
#pragma unroll
            for (int q = 0; q < 4; q++) acc[i][j][q] = 0.f;

    // chunk sources
    const float* Xs4[4] = { g_q + head + (size_t)i0 * Dc,      g_q + head + (size_t)i0 * Dc + 32,
                            g_tk + head + (size_t)i0 * Dc,     g_tk + head + (size_t)i0 * Dc + 32 };
    const float* Ys4[4] = { g_k + head + (size_t)j0 * Dc,      g_k + head + (size_t)j0 * Dc + 32,
                            g_q + head + (size_t)j0 * Dc,      g_q + head + (size_t)j0 * Dc + 32 };

    cp_tile128(smbase, Xs4[0], Dc, tid);
    cp_tile128(smbase + AWORDS * 4, Ys4[0], Dc, tid);
    CP_COMMIT();

    for (int c = 0; c < 4; ++c) {
        const int p = c & 1;
        if (c + 1 < 4) {
            const uint32_t nb = smbase + (uint32_t)(1 - p) * STG_W * 4;
            cp_tile128(nb, Xs4[c + 1], Dc, tid);
            cp_tile128(nb + AWORDS * 4, Ys4[c + 1], Dc, tid);
            CP_COMMIT();
            CP_WAIT1();
        } else {
            CP_WAIT0();
        }
        __syncthreads();
        const float* As = sm + (size_t)p * STG_W;
        compute128x128(As, As + AWORDS, acc, warp_m, warp_n, lane);
        __syncthreads();
    }

    const float scale = 1.0f / 32.0f;
    const size_t mbase = (size_t)b * Sc * Sc;
    const size_t sbase = (size_t)bh * Sc * Sc;
    const int ri = i0 + warp_m * 64 + (lane >> 2);
    const int cj = j0 + warp_n * 32 + (lane & 3) * 2;
#pragma unroll
    for (int mt = 0; mt < 4; ++mt) {
#pragma unroll
        for (int nt = 0; nt < 4; ++nt) {
            int i = ri + mt * 16;
            int j = cj + nt * 8;
            size_t m0 = mbase + (size_t)i * Sc + j;
            size_t s0 = sbase + (size_t)i * Sc + j;
            float2 mk0 = *(const float2*)(mask + m0);
            float2 mk1 = *(const float2*)(mask + m0 + 8 * (size_t)Sc);
            float2 o0 = { acc[mt][nt][0] * scale + mk0.x, acc[mt][nt][1] * scale + mk0.y };
            float2 o1 = { acc[mt][nt][2] * scale + mk1.x, acc[mt][nt][3] * scale + mk1.y };
            *(float2*)(g_scores + s0) = o0;
            *(float2*)(g_scores + s0 + 8 * (size_t)Sc) = o1;
        }
    }
}

// ---------------------------------------------------------------------------
// Row softmax over the last axis (1024 elems), one warp per row.
// ---------------------------------------------------------------------------
__global__ __launch_bounds__(256) void softmax_kernel()
{
    const int gwarp = (int)((blockIdx.x * 256 + threadIdx.x) >> 5);
    const int lane  = threadIdx.x & 31;
    float* row = g_scores + (size_t)gwarp * Sc;

    float4 v[8];
    float mx = -1e30f;
#pragma unroll
    for (int t = 0; t < 8; t++) {
        v[t] = *((const float4*)row + lane + t * 32);
        mx = fmaxf(mx, fmaxf(fmaxf(v[t].x, v[t].y), fmaxf(v[t].z, v[t].w)));
    }
#pragma unroll
    for (int o = 16; o > 0; o >>= 1) mx = fmaxf(mx, __shfl_xor_sync(0xffffffffu, mx, o));

    float sum = 0.f;
#pragma unroll
    for (int t = 0; t < 8; t++) {
        v[t].x = __expf(v[t].x - mx);
        v[t].y = __expf(v[t].y - mx);
        v[t].z = __expf(v[t].z - mx);
        v[t].w = __expf(v[t].w - mx);
        sum += v[t].x + v[t].y + v[t].z + v[t].w;
    }
#pragma unroll
    for (int o = 16; o > 0; o >>= 1) sum += __shfl_xor_sync(0xffffffffu, sum, o);

    const float inv = 1.0f / sum;
#pragma unroll
    for (int t = 0; t < 8; t++) {
        v[t].x *= inv; v[t].y *= inv; v[t].z *= inv; v[t].w *= inv;
        *((float4*)row + lane + t * 32) = v[t];
    }
}

// ---------------------------------------------------------------------------
// Context: ctx[b,i,h*64+d] = sum_j P[bh,i,j]*vv[b,j,h*64+d]. 128i x 64d / CTA.
// ---------------------------------------------------------------------------
__global__ __launch_bounds__(256) void ctx_mma()
{
    extern __shared__ float sm[];
    const uint32_t smbase = smem_u32(sm);

    const int tid = threadIdx.x, lane = tid & 31, wid = tid >> 5;
    const int warp_m = wid >> 2, warp_n = wid & 3;
    const int bh = blockIdx.z;
    const int b  = bh >> 4, h = bh & 15;
    const int i0 = blockIdx.x * 128;
    const size_t pbase = (size_t)bh * Sc * Sc;
    const size_t vbase = (size_t)b * Sc * Dc + (size_t)h * DKc;

    const int lr = lane >> 2, lc = lane & 3;

    float acc[4][2][4];
#pragma unroll
    for (int i = 0; i < 4; i++)
#pragma unroll
        for (int j = 0; j < 2; j++)
#pragma unroll
            for (int q = 0; q < 4; q++) acc[i][j][q] = 0.f;

    cp_tile128(smbase, g_scores + pbase + (size_t)i0 * Sc, Sc, tid);
    cp_tilevv(smbase + AWORDS * 4, g_vv + vbase, Dc, tid);
    CP_COMMIT();

    for (int c = 0; c < 32; ++c) {
        const int p = c & 1;
        if (c + 1 < 32) {
            const uint32_t nb = smbase + (uint32_t)(1 - p) * CTXSTG_W * 4;
            cp_tile128(nb, g_scores + pbase + (size_t)i0 * Sc + (c + 1) * 32, Sc, tid);
            cp_tilevv(nb + AWORDS * 4, g_vv + vbase + (size_t)(c + 1) * 32 * Dc, Dc, tid);
            CP_COMMIT();
            CP_WAIT1();
        } else {
            CP_WAIT0();
        }
        __syncthreads();
        const float* As = sm + (size_t)p * CTXSTG_W;
        const float* Vs = As + AWORDS;
#pragma unroll
        for (int s = 0; s < 4; ++s) {
            const int kk = s * 8 + lc;
            uint32_t bfr[2][2];
#pragma unroll
            for (int nt = 0; nt < 2; ++nt) {
                int n = warp_n * 16 + nt * 8 + lr;
                bfr[nt][0] = f2tf32(Vs[kk * PAD_VV + n]);
                bfr[nt][1] = f2tf32(Vs[(kk + 4) * PAD_VV + n]);
            }
#pragma unroll
            for (int mt = 0; mt < 4; ++mt) {
                int m = warp_m * 64 + mt * 16 + lr;
                uint32_t a[4];
                a[0] = f2tf32(As[m * PAD_AB + kk]);
                a[1] = f2tf32(As[(m + 8) * PAD_AB + kk]);
                a[2] = f2tf32(As[m * PAD_AB + kk + 4]);
                a[3] = f2tf32(As[(m + 8) * PAD_AB + kk + 4]);
#pragma unroll
                for (int nt = 0; nt < 2; ++nt) mma_tf32(acc[mt][nt], a, bfr[nt]);
            }
        }
        __syncthreads();
    }

    const int ri = i0 + warp_m * 64 + (lane >> 2);
    const int cd = warp_n * 16 + (lane & 3) * 2;
#pragma unroll
    for (int mt = 0; mt < 4; ++mt) {
#pragma unroll
        for (int nt = 0; nt < 2; ++nt) {
            int i = ri + mt * 16;
            int d = cd + nt * 8;
            size_t off0 = vbase + (size_t)i * Dc + d;
            size_t off1 = off0 + 8 * (size_t)Dc;
            float2 o0 = { acc[mt][nt][0], acc[mt][nt][1] };
            float2 o1 = { acc[mt][nt][2], acc[mt][nt][3] };
            *(float2*)(g_ctx + off0) = o0;
            *(float2*)(g_ctx + off1) = o1;
        }
    }
}

// ---------------------------------------------------------------------------
// Launch
// ---------------------------------------------------------------------------
#define GEMM_SMEM (2 * STG_W * 4)      // 73728 bytes
#define CTX_SMEM  (2 * CTXSTG_W * 4)   // 55296 bytes

extern "C" void kernel_launch(void* const* d_in, const int* in_sizes, int n_in,
                              void* d_out, int out_size)
{
    (void)in_sizes; (void)n_in; (void)out_size;
    const float* query  = (const float*)d_in[0];
    const float* key_   = (const float*)d_in[1];
    const float* value  = (const float*)d_in[2];
    const float* time_k = (const float*)d_in[3];
    const float* time_v = (const float*)d_in[4];
    const float* mask   = (const float*)d_in[5];
    const float* Wq  = (const float*)d_in[6];  const float* bq  = (const float*)d_in[7];
    const float* Wk  = (const float*)d_in[8];  const float* bk  = (const float*)d_in[9];
    const float* Wv  = (const float*)d_in[10]; const float* bv  = (const float*)d_in[11];
    const float* Wtk = (const float*)d_in[12]; const float* btk = (const float*)d_in[13];
    const float* Wtv = (const float*)d_in[14]; const float* btv = (const float*)d_in[15];
    const float* Wm  = (const float*)d_in[16]; const float* bm  = (const float*)d_in[17];
    float* out = (float*)d_out;

    float *pq, *pk, *ptk, *pvv, *pctx, *pwt;
    cudaGetSymbolAddress((void**)&pq,   g_q);
    cudaGetSymbolAddress((void**)&pk,   g_k);
    cudaGetSymbolAddress((void**)&ptk,  g_tk);
    cudaGetSymbolAddress((void**)&pvv,  g_vv);
    cudaGetSymbolAddress((void**)&pctx, g_ctx);
    cudaGetSymbolAddress((void**)&pwt,  g_wt);

    cudaFuncSetAttribute(gemm_tf32_mma, cudaFuncAttributeMaxDynamicSharedMemorySize, GEMM_SMEM);
    cudaFuncSetAttribute(scores_mma,    cudaFuncAttributeMaxDynamicSharedMemorySize, GEMM_SMEM);
    cudaFuncSetAttribute(ctx_mma,       cudaFuncAttributeMaxDynamicSharedMemorySize, CTX_SMEM);

    // Transpose all 6 weight matrices: order Wq, Wk, Wtk, Wv, Wtv, Wm
    transpose6_kernel<<<dim3(32, 32, 6), dim3(32, 8)>>>(Wq, Wk, Wtk, Wv, Wtv, Wm);

    const size_t WSZ = 1024u * 1024u;
    dim3 gg(Dc / 128, Mrows / 128);   // (8, 32)

    // Projections (tf32 mma.sync)
    gemm_tf32_mma<<<gg, 256, GEMM_SMEM>>>(query,  pwt + 0 * WSZ, bq,  pq,  0);
    gemm_tf32_mma<<<gg, 256, GEMM_SMEM>>>(key_,   pwt + 1 * WSZ, bk,  pk,  0);
    gemm_tf32_mma<<<gg, 256, GEMM_SMEM>>>(time_k, pwt + 2 * WSZ, btk, ptk, 0);
    gemm_tf32_mma<<<gg, 256, GEMM_SMEM>>>(value,  pwt + 3 * WSZ, bv,  pvv, 0);
    gemm_tf32_mma<<<gg, 256, GEMM_SMEM>>>(time_v, pwt + 4 * WSZ, btv, pvv, 1);  // vv = v + t_v

    // Attention core (tf32 mma.sync)
    scores_mma<<<dim3(Sc / 128, Sc / 128, Bc * Hc), 256, GEMM_SMEM>>>(mask);
    softmax_kernel<<<(Bc * Hc * Sc) / 8, 256>>>();
    ctx_mma<<<dim3(Sc / 128, 1, Bc * Hc), 256, CTX_SMEM>>>();

    // Output projection
    gemm_tf32_mma<<<gg, 256, GEMM_SMEM>>>(pctx, pwt + 5 * WSZ, bm, out, 0);
}

// round 5
// speedup vs baseline: 3.2865x; 1.0659x over previous
#include <cuda_runtime.h>
#include <cstdint>
#include <cstddef>

// Problem constants
#define Bc   4
#define Sc   1024
#define Dc   1024
#define Hc   16
#define DKc  64
#define Mrows (Bc * Sc)   // 4096

// ---------------------------------------------------------------------------
// Scratch (static __device__ arrays — no allocation at runtime)
// ---------------------------------------------------------------------------
__device__ float g_q  [(size_t)Mrows * Dc];                 // 16 MB (tf32-rounded)
__device__ float g_k  [(size_t)Mrows * Dc];                 // 16 MB (tf32-rounded)
__device__ float g_tk [(size_t)Mrows * Dc];                 // 16 MB (tf32-rounded)
__device__ float g_vv [(size_t)Mrows * Dc];                 // 16 MB (v + t_v, tf32-rounded)
__device__ float g_ctx[(size_t)Mrows * Dc];                 // 16 MB (tf32-rounded)
__device__ float g_scores[(size_t)Bc * Hc * Sc * Sc];       // 256 MB
__device__ float g_wt [6u * 1024u * 1024u];                 // 24 MB (transposed, tf32-rounded)

// ---------------------------------------------------------------------------
// Helpers
// ---------------------------------------------------------------------------
__device__ __forceinline__ uint32_t smem_u32(const void* p) {
    uint32_t a;
    asm("{ .reg .u64 t; cvta.to.shared.u64 t, %1; cvt.u32.u64 %0, t; }" : "=r"(a) : "l"(p));
    return a;
}

__device__ __forceinline__ void cp16(uint32_t dst, const void* src) {
    asm volatile("cp.async.cg.shared.global [%0], [%1], 16;" :: "r"(dst), "l"(src));
}
#define CP_COMMIT() asm volatile("cp.async.commit_group;" ::: "memory")
#define CP_WAIT1()  asm volatile("cp.async.wait_group 1;" ::: "memory")
#define CP_WAIT0()  asm volatile("cp.async.wait_group 0;" ::: "memory")

__device__ __forceinline__ uint32_t f2tf32(float f) {
    uint32_t o;
    asm("cvt.rna.tf32.f32 %0, %1;" : "=r"(o) : "f"(f));
    return o;
}
__device__ __forceinline__ float roundtf(float f) { return __uint_as_float(f2tf32(f)); }

__device__ __forceinline__ void mma_tf32(float d[4], const uint32_t a[4], const uint32_t b[2]) {
    asm volatile("mma.sync.aligned.m16n8k8.row.col.f32.tf32.tf32.f32 "
        "{%0,%1,%2,%3}, {%4,%5,%6,%7}, {%8,%9}, {%0,%1,%2,%3};"
        : "+f"(d[0]), "+f"(d[1]), "+f"(d[2]), "+f"(d[3])
        : "r"(a[0]), "r"(a[1]), "r"(a[2]), "r"(a[3]), "r"(b[0]), "r"(b[1]));
}

__device__ __forceinline__ void ldm4(uint32_t r[4], uint32_t addr) {
    asm volatile("ldmatrix.sync.aligned.m8n8.x4.shared.b16 {%0,%1,%2,%3}, [%4];"
        : "=r"(r[0]), "=r"(r[1]), "=r"(r[2]), "=r"(r[3]) : "r"(addr));
}

// Padded strides (words). 36 => ldmatrix rows hit all 32 banks once.
#define PAD_AB  36
#define AWORDS  (128 * PAD_AB)      // 4608
#define STG_W   (2 * AWORDS)        // 9216 words per stage (A + B)
#define PAD_VV  72
#define VWORDS  (32 * PAD_VV)       // 2304
#define CTXSTG_W (AWORDS + VWORDS)  // 6912

// ---------------------------------------------------------------------------
// Transpose + tf32-round: g_wt[z] = round_tf32(W_z^T)
// ---------------------------------------------------------------------------
__global__ __launch_bounds__(256) void transpose6_kernel(
    const float* __restrict__ W0, const float* __restrict__ W1,
    const float* __restrict__ W2, const float* __restrict__ W3,
    const float* __restrict__ W4, const float* __restrict__ W5)
{
    __shared__ float tile[32][33];
    const float* src;
    switch (blockIdx.z) {
        case 0: src = W0; break; case 1: src = W1; break;
        case 2: src = W2; break; case 3: src = W3; break;
        case 4: src = W4; break; default: src = W5; break;
    }
    float* dst = g_wt + (size_t)blockIdx.z * 1024u * 1024u;

    int tx = threadIdx.x, ty = threadIdx.y;
    int x = blockIdx.x * 32 + tx;
    int y = blockIdx.y * 32 + ty;
#pragma unroll
    for (int j = 0; j < 32; j += 8)
        tile[ty + j][tx] = src[(size_t)(y + j) * 1024 + x];
    __syncthreads();
    int x2 = blockIdx.y * 32 + tx;
    int y2 = blockIdx.x * 32 + ty;
#pragma unroll
    for (int j = 0; j < 32; j += 8)
        dst[(size_t)(y2 + j) * 1024 + x2] = roundtf(tile[tx][ty + j]);
}

// ---------------------------------------------------------------------------
// cp.async staging
// ---------------------------------------------------------------------------
__device__ __forceinline__ void cp_tile128(uint32_t smbase, const float* __restrict__ src,
                                           size_t ldg, int tid) {
#pragma unroll
    for (int t = 0; t < 4; ++t) {
        int slot = tid + t * 256;
        int row = slot >> 3;
        int seg = slot & 7;
        cp16(smbase + (uint32_t)(row * PAD_AB + seg * 4) * 4,
             src + (size_t)row * ldg + seg * 4);
    }
}

__device__ __forceinline__ void cp_tilevv(uint32_t smbase, const float* __restrict__ src,
                                          size_t ldg, int tid) {
#pragma unroll
    for (int t = 0; t < 2; ++t) {
        int slot = tid + t * 256;
        int row = slot >> 4;        // k 0..31
        int seg = slot & 15;
        cp16(smbase + (uint32_t)(row * PAD_VV + seg * 4) * 4,
             src + (size_t)row * ldg + seg * 4);
    }
}

// ---------------------------------------------------------------------------
// Compute one 32-k chunk of 128x128 via ldmatrix. CVTA: round A-side fragments.
// ---------------------------------------------------------------------------
template<int CVTA>
__device__ __forceinline__ void compute128x128(uint32_t Asm, uint32_t Bsm,
                                               float acc[4][4][4],
                                               int warp_m, int warp_n, int lane) {
    const int t = lane >> 3, r = lane & 7;
    // A tiles: t0=(m-lo,k-lo) t1=(m-hi,k-lo) t2=(m-lo,k-hi) t3=(m-hi,k-hi)
    const uint32_t Aaddr0 = Asm +
        (uint32_t)((warp_m * 64 + (t & 1) * 8 + r) * PAD_AB + (t >> 1) * 4) * 4;
    // B tiles: t0=(nt even,k-lo) t1=(nt even,k-hi) t2=(nt odd,k-lo) t3=(nt odd,k-hi)
    const uint32_t Baddr0 = Bsm +
        (uint32_t)((warp_n * 32 + (t >> 1) * 8 + r) * PAD_AB + (t & 1) * 4) * 4;

#pragma unroll
    for (int s = 0; s < 4; ++s) {
        uint32_t bfr[2][4];
        ldm4(bfr[0], Baddr0 + s * 32);                          // nt 0,1
        ldm4(bfr[1], Baddr0 + 16 * PAD_AB * 4 + s * 32);        // nt 2,3
#pragma unroll
        for (int mt = 0; mt < 4; ++mt) {
            uint32_t a[4];
            ldm4(a, Aaddr0 + (uint32_t)(mt * 16 * PAD_AB) * 4 + s * 32);
            if (CVTA) {
#pragma unroll
                for (int e = 0; e < 4; ++e) a[e] = f2tf32(__uint_as_float(a[e]));
            }
#pragma unroll
            for (int nt = 0; nt < 4; ++nt) {
                const uint32_t b2[2] = { bfr[nt >> 1][(nt & 1) * 2],
                                         bfr[nt >> 1][(nt & 1) * 2 + 1] };
                mma_tf32(acc[mt][nt], a, b2);
            }
        }
    }
}

// ---------------------------------------------------------------------------
// GEMM: C = A @ BT^T + bias (+C if accFlag). 128x128 per CTA.
// CVTA: round A fragments (raw fp32 inputs). ROUND: tf32-round the stores.
// ---------------------------------------------------------------------------
template<int CVTA, int ROUND>
__global__ __launch_bounds__(256) void gemm_tf32_mma(
    const float* __restrict__ A, const float* __restrict__ BT,
    const float* __restrict__ bias, float* __restrict__ C, int accFlag)
{
    extern __shared__ float sm[];
    const uint32_t smbase = smem_u32(sm);

    const int tid = threadIdx.x, lane = tid & 31, wid = tid >> 5;
    const int warp_m = wid >> 2, warp_n = wid & 3;
    const int bm = blockIdx.y * 128, bn = blockIdx.x * 128;

    float acc[4][4][4];
#pragma unroll
    for (int i = 0; i < 4; i++)
#pragma unroll
        for (int j = 0; j < 4; j++)
#pragma unroll
            for (int q = 0; q < 4; q++) acc[i][j][q] = 0.f;

    cp_tile128(smbase, A + (size_t)bm * Dc, Dc, tid);
    cp_tile128(smbase + AWORDS * 4, BT + (size_t)bn * Dc, Dc, tid);
    CP_COMMIT();

    for (int c = 0; c < 32; ++c) {
        const int p = c & 1;
        if (c + 1 < 32) {
            const uint32_t nb = smbase + (uint32_t)(1 - p) * STG_W * 4;
            cp_tile128(nb, A + (size_t)bm * Dc + (c + 1) * 32, Dc, tid);
            cp_tile128(nb + AWORDS * 4, BT + (size_t)bn * Dc + (c + 1) * 32, Dc, tid);
            CP_COMMIT();
            CP_WAIT1();
        } else {
            CP_WAIT0();
        }
        __syncthreads();
        const uint32_t As = smbase + (uint32_t)p * STG_W * 4;
        compute128x128<CVTA>(As, As + AWORDS * 4, acc, warp_m, warp_n, lane);
        __syncthreads();
    }

    const int r0 = bm + warp_m * 64 + (lane >> 2);
    const int c0 = bn + warp_n * 32 + (lane & 3) * 2;
#pragma unroll
    for (int mt = 0; mt < 4; ++mt) {
#pragma unroll
        for (int nt = 0; nt < 4; ++nt) {
            int col = c0 + nt * 8;
            float2 bv = *(const float2*)(bias + col);
            size_t off0 = (size_t)(r0 + mt * 16) * Dc + col;
            size_t off1 = off0 + 8 * (size_t)Dc;
            float2 o0 = { acc[mt][nt][0] + bv.x, acc[mt][nt][1] + bv.y };
            float2 o1 = { acc[mt][nt][2] + bv.x, acc[mt][nt][3] + bv.y };
            if (accFlag) {
                float2 p0 = *(const float2*)(C + off0);
                float2 p1 = *(const float2*)(C + off1);
                o0.x += p0.x; o0.y += p0.y; o1.x += p1.x; o1.y += p1.y;
            }
            if (ROUND) {
                o0.x = roundtf(o0.x); o0.y = roundtf(o0.y);
                o1.x = roundtf(o1.x); o1.y = roundtf(o1.y);
            }
            *(float2*)(C + off0) = o0;
            *(float2*)(C + off1) = o1;
        }
    }
}

// ---------------------------------------------------------------------------
// Scores: scores[bh,i,j] = (q_i.k_j + tk_i.q_j)/32 + mask. 128x128 per CTA.
// Inputs pre-rounded -> no cvt anywhere.
// ---------------------------------------------------------------------------
__global__ __launch_bounds__(256) void scores_mma(const float* __restrict__ mask)
{
    extern __shared__ float sm[];
    const uint32_t smbase = smem_u32(sm);

    const int tid = threadIdx.x, lane = tid & 31, wid = tid >> 5;
    const int warp_m = wid >> 2, warp_n = wid & 3;
    const int bh = blockIdx.z;
    const int b  = bh >> 4, h = bh & 15;
    const int i0 = blockIdx.y * 128, j0 = blockIdx.x * 128;
    const size_t head = (size_t)b * Sc * Dc + (size_t)h * DKc;

    float acc[4][4][4];
#pragma unroll
    for (int i = 0; i < 4; i++)
#pragma unroll
        for (int j = 0; j < 4; j++)
#pragma unroll
            for (int q = 0; q < 4; q++) acc[i][j][q] = 0.f;

    const float* Xs4[4] = { g_q + head + (size_t)i0 * Dc,   g_q + head + (size_t)i0 * Dc + 32,
                            g_tk + head + (size_t)i0 * Dc,  g_tk + head + (size_t)i0 * Dc + 32 };
    const float* Ys4[4] = { g_k + head + (size_t)j0 * Dc,   g_k + head + (size_t)j0 * Dc + 32,
                            g_q + head + (size_t)j0 * Dc,   g_q + head + (size_t)j0 * Dc + 32 };

    cp_tile128(smbase, Xs4[0], Dc, tid);
    cp_tile128(smbase + AWORDS * 4, Ys4[0], Dc, tid);
    CP_COMMIT();

    for (int c = 0; c < 4; ++c) {
        const int p = c & 1;
        if (c + 1 < 4) {
            const uint32_t nb = smbase + (uint32_t)(1 - p) * STG_W * 4;
            cp_tile128(nb, Xs4[c + 1], Dc, tid);
            cp_tile128(nb + AWORDS * 4, Ys4[c + 1], Dc, tid);
            CP_COMMIT();
            CP_WAIT1();
        } else {
            CP_WAIT0();
        }
        __syncthreads();
        const uint32_t As = smbase + (uint32_t)p * STG_W * 4;
        compute128x128<0>(As, As + AWORDS * 4, acc, warp_m, warp_n, lane);
        __syncthreads();
    }

    const float scale = 1.0f / 32.0f;
    const size_t mbase = (size_t)b * Sc * Sc;
    const size_t sbase = (size_t)bh * Sc * Sc;
    const int ri = i0 + warp_m * 64 + (lane >> 2);
    const int cj = j0 + warp_n * 32 + (lane & 3) * 2;
#pragma unroll
    for (int mt = 0; mt < 4; ++mt) {
#pragma unroll
        for (int nt = 0; nt < 4; ++nt) {
            int i = ri + mt * 16;
            int j = cj + nt * 8;
            size_t m0 = mbase + (size_t)i * Sc + j;
            size_t s0 = sbase + (size_t)i * Sc + j;
            float2 mk0 = *(const float2*)(mask + m0);
            float2 mk1 = *(const float2*)(mask + m0 + 8 * (size_t)Sc);
            float2 o0 = { acc[mt][nt][0] * scale + mk0.x, acc[mt][nt][1] * scale + mk0.y };
            float2 o1 = { acc[mt][nt][2] * scale + mk1.x, acc[mt][nt][3] * scale + mk1.y };
            *(float2*)(g_scores + s0) = o0;
            *(float2*)(g_scores + s0 + 8 * (size_t)Sc) = o1;
        }
    }
}

// ---------------------------------------------------------------------------
// Row softmax (1024 elems), one warp per row. Writes tf32-rounded probs.
// ---------------------------------------------------------------------------
__global__ __launch_bounds__(256) void softmax_kernel()
{
    const int gwarp = (int)((blockIdx.x * 256 + threadIdx.x) >> 5);
    const int lane  = threadIdx.x & 31;
    float* row = g_scores + (size_t)gwarp * Sc;

    float4 v[8];
    float mx = -1e30f;
#pragma unroll
    for (int t = 0; t < 8; t++) {
        v[t] = *((const float4*)row + lane + t * 32);
        mx = fmaxf(mx, fmaxf(fmaxf(v[t].x, v[t].y), fmaxf(v[t].z, v[t].w)));
    }
#pragma unroll
    for (int o = 16; o > 0; o >>= 1) mx = fmaxf(mx, __shfl_xor_sync(0xffffffffu, mx, o));

    float sum = 0.f;
#pragma unroll
    for (int t = 0; t < 8; t++) {
        v[t].x = __expf(v[t].x - mx);
        v[t].y = __expf(v[t].y - mx);
        v[t].z = __expf(v[t].z - mx);
        v[t].w = __expf(v[t].w - mx);
        sum += v[t].x + v[t].y + v[t].z + v[t].w;
    }
#pragma unroll
    for (int o = 16; o > 0; o >>= 1) sum += __shfl_xor_sync(0xffffffffu, sum, o);

    const float inv = 1.0f / sum;
#pragma unroll
    for (int t = 0; t < 8; t++) {
        v[t].x = roundtf(v[t].x * inv);
        v[t].y = roundtf(v[t].y * inv);
        v[t].z = roundtf(v[t].z * inv);
        v[t].w = roundtf(v[t].w * inv);
        *((float4*)row + lane + t * 32) = v[t];
    }
}

// ---------------------------------------------------------------------------
// Context: ctx[b,i,h*64+d] = sum_j P[bh,i,j]*vv[b,j,h*64+d]. 128i x 64d / CTA.
// A via ldmatrix (pre-rounded probs), B scalar conflict-free LDS (pre-rounded vv).
// ---------------------------------------------------------------------------
__global__ __launch_bounds__(256) void ctx_mma()
{
    extern __shared__ float sm[];
    const uint32_t smbase = smem_u32(sm);

    const int tid = threadIdx.x, lane = tid & 31, wid = tid >> 5;
    const int warp_m = wid >> 2, warp_n = wid & 3;
    const int bh = blockIdx.z;
    const int b  = bh >> 4, h = bh & 15;
    const int i0 = blockIdx.x * 128;
    const size_t pbase = (size_t)bh * Sc * Sc;
    const size_t vbase = (size_t)b * Sc * Dc + (size_t)h * DKc;

    const int lr = lane >> 2, lc = lane & 3;
    const int lt = lane >> 3, lrr = lane & 7;

    float acc[4][2][4];
#pragma unroll
    for (int i = 0; i < 4; i++)
#pragma unroll
        for (int j = 0; j < 2; j++)
#pragma unroll
            for (int q = 0; q < 4; q++) acc[i][j][q] = 0.f;

    cp_tile128(smbase, g_scores + pbase + (size_t)i0 * Sc, Sc, tid);
    cp_tilevv(smbase + AWORDS * 4, g_vv + vbase, Dc, tid);
    CP_COMMIT();

    for (int c = 0; c < 32; ++c) {
        const int p = c & 1;
        if (c + 1 < 32) {
            const uint32_t nb = smbase + (uint32_t)(1 - p) * CTXSTG_W * 4;
            cp_tile128(nb, g_scores + pbase + (size_t)i0 * Sc + (c + 1) * 32, Sc, tid);
            cp_tilevv(nb + AWORDS * 4, g_vv + vbase + (size_t)(c + 1) * 32 * Dc, Dc, tid);
            CP_COMMIT();
            CP_WAIT1();
        } else {
            CP_WAIT0();
        }
        __syncthreads();
        const uint32_t Abase = smbase + (uint32_t)p * CTXSTG_W * 4;
        const float* Vs = sm + (size_t)p * CTXSTG_W + AWORDS;
        const uint32_t Aaddr0 = Abase +
            (uint32_t)((warp_m * 64 + (lt & 1) * 8 + lrr) * PAD_AB + (lt >> 1) * 4) * 4;
#pragma unroll
        for (int s = 0; s < 4; ++s) {
            const int kk = s * 8 + lc;
            uint32_t bfr[2][2];
#pragma unroll
            for (int nt = 0; nt < 2; ++nt) {
                int n = warp_n * 16 + nt * 8 + lr;
                bfr[nt][0] = __float_as_uint(Vs[kk * PAD_VV + n]);
                bfr[nt][1] = __float_as_uint(Vs[(kk + 4) * PAD_VV + n]);
            }
#pragma unroll
            for (int mt = 0; mt < 4; ++mt) {
                uint32_t a[4];
                ldm4(a, Aaddr0 + (uint32_t)(mt * 16 * PAD_AB) * 4 + s * 32);
#pragma unroll
                for (int nt = 0; nt < 2; ++nt) mma_tf32(acc[mt][nt], a, bfr[nt]);
            }
        }
        __syncthreads();
    }

    const int ri = i0 + warp_m * 64 + (lane >> 2);
    const int cd = warp_n * 16 + (lane & 3) * 2;
#pragma unroll
    for (int mt = 0; mt < 4; ++mt) {
#pragma unroll
        for (int nt = 0; nt < 2; ++nt) {
            int i = ri + mt * 16;
            int d = cd + nt * 8;
            size_t off0 = vbase + (size_t)i * Dc + d;
            size_t off1 = off0 + 8 * (size_t)Dc;
            float2 o0 = { roundtf(acc[mt][nt][0]), roundtf(acc[mt][nt][1]) };
            float2 o1 = { roundtf(acc[mt][nt][2]), roundtf(acc[mt][nt][3]) };
            *(float2*)(g_ctx + off0) = o0;
            *(float2*)(g_ctx + off1) = o1;
        }
    }
}

// ---------------------------------------------------------------------------
// Launch
// ---------------------------------------------------------------------------
#define GEMM_SMEM (2 * STG_W * 4)      // 73728 bytes
#define CTX_SMEM  (2 * CTXSTG_W * 4)   // 55296 bytes

extern "C" void kernel_launch(void* const* d_in, const int* in_sizes, int n_in,
                              void* d_out, int out_size)
{
    (void)in_sizes; (void)n_in; (void)out_size;
    const float* query  = (const float*)d_in[0];
    const float* key_   = (const float*)d_in[1];
    const float* value  = (const float*)d_in[2];
    const float* time_k = (const float*)d_in[3];
    const float* time_v = (const float*)d_in[4];
    const float* mask   = (const float*)d_in[5];
    const float* Wq  = (const float*)d_in[6];  const float* bq  = (const float*)d_in[7];
    const float* Wk  = (const float*)d_in[8];  const float* bk  = (const float*)d_in[9];
    const float* Wv  = (const float*)d_in[10]; const float* bv  = (const float*)d_in[11];
    const float* Wtk = (const float*)d_in[12]; const float* btk = (const float*)d_in[13];
    const float* Wtv = (const float*)d_in[14]; const float* btv = (const float*)d_in[15];
    const float* Wm  = (const float*)d_in[16]; const float* bm  = (const float*)d_in[17];
    float* out = (float*)d_out;

    float *pq, *pk, *ptk, *pvv, *pctx, *pwt;
    cudaGetSymbolAddress((void**)&pq,   g_q);
    cudaGetSymbolAddress((void**)&pk,   g_k);
    cudaGetSymbolAddress((void**)&ptk,  g_tk);
    cudaGetSymbolAddress((void**)&pvv,  g_vv);
    cudaGetSymbolAddress((void**)&pctx, g_ctx);
    cudaGetSymbolAddress((void**)&pwt,  g_wt);

    cudaFuncSetAttribute((const void*)gemm_tf32_mma<1,1>, cudaFuncAttributeMaxDynamicSharedMemorySize, GEMM_SMEM);
    cudaFuncSetAttribute((const void*)gemm_tf32_mma<0,0>, cudaFuncAttributeMaxDynamicSharedMemorySize, GEMM_SMEM);
    cudaFuncSetAttribute((const void*)scores_mma, cudaFuncAttributeMaxDynamicSharedMemorySize, GEMM_SMEM);
    cudaFuncSetAttribute((const void*)ctx_mma,    cudaFuncAttributeMaxDynamicSharedMemorySize, CTX_SMEM);

    // Transpose + round all 6 weight matrices: order Wq, Wk, Wtk, Wv, Wtv, Wm
    transpose6_kernel<<<dim3(32, 32, 6), dim3(32, 8)>>>(Wq, Wk, Wtk, Wv, Wtv, Wm);

    const size_t WSZ = 1024u * 1024u;
    dim3 gg(Dc / 128, Mrows / 128);   // (8, 32)

    // Projections: raw fp32 A (cvt in-loop), rounded outputs
    gemm_tf32_mma<1,1><<<gg, 256, GEMM_SMEM>>>(query,  pwt + 0 * WSZ, bq,  pq,  0);
    gemm_tf32_mma<1,1><<<gg, 256, GEMM_SMEM>>>(key_,   pwt + 1 * WSZ, bk,  pk,  0);
    gemm_tf32_mma<1,1><<<gg, 256, GEMM_SMEM>>>(time_k, pwt + 2 * WSZ, btk, ptk, 0);
    gemm_tf32_mma<1,1><<<gg, 256, GEMM_SMEM>>>(value,  pwt + 3 * WSZ, bv,  pvv, 0);
    gemm_tf32_mma<1,1><<<gg, 256, GEMM_SMEM>>>(time_v, pwt + 4 * WSZ, btv, pvv, 1); // vv = v + t_v

    // Attention core
    scores_mma<<<dim3(Sc / 128, Sc / 128, Bc * Hc), 256, GEMM_SMEM>>>(mask);
    softmax_kernel<<<(Bc * Hc * Sc) / 8, 256>>>();
    ctx_mma<<<dim3(Sc / 128, 1, Bc * Hc), 256, CTX_SMEM>>>();

    // Output projection: pre-rounded A, full-precision output
    gemm_tf32_mma<0,0><<<gg, 256, GEMM_SMEM>>>(pctx, pwt + 5 * WSZ, bm, out, 0);
}